// round 9
// baseline (speedup 1.0000x reference)
#include <cuda_runtime.h>
#include <stdint.h>
#include <math.h>

// Problem constants: B=2, N=2048 -> T=4096 tokens, D=1024, E=8, H=2048, K=2
#define Tn 4096
#define Dd 1024
#define Ee 8
#define Hh 2048

// GEMM tile config (verified R4 core)
#define BM 128
#define BN 256
#define BK 16
#define STAGES 3
#define ASTR 20                      // A smem row stride (floats), conflict-free
#define BSTR 264                     // B smem row stride (floats), == 8 mod 32
#define ASZ (BM * ASTR)              // 2560 floats / stage
#define BSZ (BK * BSTR)              // 4224 floats / stage
#define SMEM_FLOATS (STAGES * (ASZ + BSZ))   // 20352 floats = 81408 B

// ---------------- device scratch (allocation-free rule: __device__ globals) --
__device__ int   g_cnt[Ee];
__device__ int   g_list[Ee * Tn];            // pair slot (= token*2 + k) per expert row
__device__ float g_gate[Tn * 2];
__device__ float g_ent[Tn];
__device__ float g_h[(size_t)Ee * Tn * Hh];  // hidden activations (tf32-rounded)
__device__ float g_y[(size_t)Tn * 2 * Dd];   // per-pair expert outputs
__device__ float g_xt[(size_t)Tn * Dd];      // x, tf32-rounded (same layout)
__device__ float g_w1r[(size_t)Ee * Dd * Hh];// w1, tf32-rounded (same layout)
__device__ float g_w2r[(size_t)Ee * Hh * Dd];// w2, tf32-rounded (same layout)

// -------------------------------------------------------------- helpers -----
__device__ __forceinline__ float f2tf_f(float x) {
    uint32_t r;
    asm("cvt.rna.tf32.f32 %0, %1;" : "=r"(r) : "f"(x));
    return __uint_as_float(r);
}
__device__ __forceinline__ void cp16(float* s, const float* g) {
    uint32_t sa = (uint32_t)__cvta_generic_to_shared(s);
    asm volatile("cp.async.cg.shared.global [%0], [%1], 16;" :: "r"(sa), "l"(g));
}
__device__ __forceinline__ void mma8(float* c, const uint32_t* a, const uint32_t* b) {
    asm volatile(
        "mma.sync.aligned.m16n8k8.row.col.f32.tf32.tf32.f32 "
        "{%0,%1,%2,%3}, {%4,%5,%6,%7}, {%8,%9}, {%0,%1,%2,%3};"
        : "+f"(c[0]), "+f"(c[1]), "+f"(c[2]), "+f"(c[3])
        : "r"(a[0]), "r"(a[1]), "r"(a[2]), "r"(a[3]), "r"(b[0]), "r"(b[1]));
}

// ---------------------------------------------------------------- init ------
__global__ void init_kernel() {
    if (threadIdx.x < Ee) g_cnt[threadIdx.x] = 0;
}

// ------------------------------------------------------------- routing ------
__global__ void routing_kernel(const float* __restrict__ x,
                               const float* __restrict__ wg,
                               const float* __restrict__ bg) {
    const int t    = blockIdx.x * 8 + (threadIdx.x >> 5);
    const int lane = threadIdx.x & 31;
    if (t >= Tn) return;

    float acc[Ee];
#pragma unroll
    for (int e = 0; e < Ee; e++) acc[e] = 0.f;

    const float* xr = x + (size_t)t * Dd;
    for (int c = lane; c < Dd; c += 32) {
        const float xv = xr[c];
        const float4* w4 = reinterpret_cast<const float4*>(wg + (size_t)c * Ee);
        const float4 a = w4[0];
        const float4 b = w4[1];
        acc[0] += xv * a.x; acc[1] += xv * a.y; acc[2] += xv * a.z; acc[3] += xv * a.w;
        acc[4] += xv * b.x; acc[5] += xv * b.y; acc[6] += xv * b.z; acc[7] += xv * b.w;
    }
#pragma unroll
    for (int off = 16; off; off >>= 1) {
#pragma unroll
        for (int e = 0; e < Ee; e++)
            acc[e] += __shfl_xor_sync(0xffffffffu, acc[e], off);
    }

    if (lane == 0) {
        float l[Ee];
#pragma unroll
        for (int e = 0; e < Ee; e++) l[e] = acc[e] + bg[e];

        // top-2 (ties -> lowest index, matching jax.lax.top_k)
        int i0 = 0; float v0 = l[0];
#pragma unroll
        for (int e = 1; e < Ee; e++) if (l[e] > v0) { v0 = l[e]; i0 = e; }
        int i1 = -1; float v1 = -3.4e38f;
#pragma unroll
        for (int e = 0; e < Ee; e++)
            if (e != i0 && l[e] > v1) { v1 = l[e]; i1 = e; }

        const float e1 = expf(v1 - v0);
        const float inv = 1.f / (1.f + e1);
        const float gv0 = inv;
        const float gv1 = e1 * inv;

        g_ent[t] = -(gv0 * logf(fmaxf(gv0, 1e-8f)) +
                     gv1 * logf(fmaxf(gv1, 1e-8f)));

        int p0 = atomicAdd(&g_cnt[i0], 1);
        g_list[i0 * Tn + p0] = t * 2 + 0;
        g_gate[t * 2 + 0] = gv0;

        int p1 = atomicAdd(&g_cnt[i1], 1);
        g_list[i1 * Tn + p1] = t * 2 + 1;
        g_gate[t * 2 + 1] = gv1;
    }
}

// ------------------------------------------------- entropy (deterministic) --
__global__ void entropy_kernel(float* __restrict__ out, int do_write) {
    __shared__ float sh[1024];
    const int t = threadIdx.x;
    float s = 0.f;
    for (int i = t; i < Tn; i += 1024) s += g_ent[i];
    sh[t] = s;
    __syncthreads();
    for (int o = 512; o; o >>= 1) {
        if (t < o) sh[t] += sh[t + o];
        __syncthreads();
    }
    if (t == 0 && do_write) out[(size_t)Tn * Dd] = sh[0] / (float)Tn;
}

// --------------------------------------------- tf32 pre-round (elementwise) -
__global__ void round_x_kernel(const float* __restrict__ x) {
    const int idx = blockIdx.x * 256 + threadIdx.x;       // over Tn*Dd/4
    float4 v = ((const float4*)x)[idx];
    v.x = f2tf_f(v.x); v.y = f2tf_f(v.y); v.z = f2tf_f(v.z); v.w = f2tf_f(v.w);
    ((float4*)g_xt)[idx] = v;
}
__global__ void round_w1_kernel(const float* __restrict__ w1) {
    const size_t idx = (size_t)blockIdx.x * 256 + threadIdx.x;   // over E*D*H/4
    float4 v = ((const float4*)w1)[idx];
    v.x = f2tf_f(v.x); v.y = f2tf_f(v.y); v.z = f2tf_f(v.z); v.w = f2tf_f(v.w);
    ((float4*)g_w1r)[idx] = v;
}
__global__ void round_w2_kernel(const float* __restrict__ w2) {
    const size_t idx = (size_t)blockIdx.x * 256 + threadIdx.x;   // over E*H*D/4
    float4 v = ((const float4*)w2)[idx];
    v.x = f2tf_f(v.x); v.y = f2tf_f(v.y); v.z = f2tf_f(v.z); v.w = f2tf_f(v.w);
    ((float4*)g_w2r)[idx] = v;
}

// ----------------------------------------------------- tf32 grouped GEMM ----
// Verified R4 core; operands pre-rounded to tf32 in gmem, so fragment loads
// are raw bit reinterprets (no CVT in the hot loop).
// C[r, col] = A[r, :] @ W_e[:, col] + bias_e[col]   (relu+round+gather if G1,
// scatter-to-pair-slot if !G1). Block 128x256, BK=16, 8 warps (2m x 4n).
template<int N, int KD, bool G1>
__global__ __launch_bounds__(256, 1)
void moe_gemm(const float* __restrict__ bias)
{
    const int e    = blockIdx.z;
    const int cnt  = g_cnt[e];
    const int row0 = blockIdx.x * BM;
    if (row0 >= cnt) return;
    const int col0 = blockIdx.y * BN;

    extern __shared__ float sm[];
    float* As = sm;                    // [STAGES][BM][ASTR]
    float* Bs = sm + STAGES * ASZ;     // [STAGES][BK][BSTR]

    const int tid  = threadIdx.x;
    const int lane = tid & 31;
    const int warp = tid >> 5;
    const int wm   = warp & 1;         // 2 warps along M
    const int wn   = warp >> 1;        // 4 warps along N

    // --- A loader: 2 rows per thread (128 rows x 4 float4 per stage) ---
    const int ar0 = tid >> 2;          // 0..63
    const int ak4 = (tid & 3) * 4;     // k offset within BK (0,4,8,12)
    const float* ap0;
    const float* ap1;
    if (G1) {
        const int t0 = g_list[e * Tn + row0 + ar0] >> 1;
        const int t1 = g_list[e * Tn + row0 + ar0 + 64] >> 1;
        ap0 = g_xt + (size_t)t0 * KD + ak4;
        ap1 = g_xt + (size_t)t1 * KD + ak4;
    } else {
        ap0 = g_h + ((size_t)e * Tn + row0 + ar0) * KD + ak4;
        ap1 = g_h + ((size_t)e * Tn + row0 + ar0 + 64) * KD + ak4;
    }

    // --- B loader: 4 float4 per thread (16 rows x 64 float4 per stage) ---
    const int brow = tid >> 6;         // 0..3
    const int bc4  = (tid & 63) * 4;   // 0..252
    const float* W = G1 ? g_w1r : g_w2r;
    const float* Wp = W + (size_t)e * KD * N + col0 + bc4;

    float acc[4][8][4];
#pragma unroll
    for (int mi = 0; mi < 4; mi++)
#pragma unroll
        for (int ni = 0; ni < 8; ni++)
#pragma unroll
            for (int j = 0; j < 4; j++) acc[mi][ni][j] = 0.f;

    auto load_stage = [&](int s, int kt) {
        float* as = As + s * ASZ;
        float* bs = Bs + s * BSZ;
        const int kg = kt * BK;
        cp16(as + ar0 * ASTR + ak4, ap0 + kg);
        cp16(as + (ar0 + 64) * ASTR + ak4, ap1 + kg);
#pragma unroll
        for (int j = 0; j < 4; j++)
            cp16(bs + (brow + j * 4) * BSTR + bc4,
                 Wp + (size_t)(kg + brow + j * 4) * N);
    };

    auto compute = [&](int s) {
        const float* as = As + s * ASZ;
        const float* bs = Bs + s * BSZ;
#pragma unroll
        for (int g = 0; g < 2; g++) {              // two k8 steps per BK=16
            uint32_t Af[4][4];
#pragma unroll
            for (int mi = 0; mi < 4; mi++) {
                const int r = wm * 64 + mi * 16 + (lane >> 2);
                const int k = g * 8 + (lane & 3);
                const float* p = as + r * ASTR + k;
                Af[mi][0] = __float_as_uint(p[0]);            // (r,   k)
                Af[mi][1] = __float_as_uint(p[8 * ASTR]);     // (r+8, k)
                Af[mi][2] = __float_as_uint(p[4]);            // (r,   k+4)
                Af[mi][3] = __float_as_uint(p[8 * ASTR + 4]); // (r+8, k+4)
            }
            uint32_t Bf[8][2];
#pragma unroll
            for (int ni = 0; ni < 8; ni++) {
                const int c = wn * 64 + ni * 8 + (lane >> 2);
                const int k = g * 8 + (lane & 3);
                const float* p = bs + k * BSTR + c;
                Bf[ni][0] = __float_as_uint(p[0]);            // (k,   c)
                Bf[ni][1] = __float_as_uint(p[4 * BSTR]);     // (k+4, c)
            }
#pragma unroll
            for (int mi = 0; mi < 4; mi++)
#pragma unroll
                for (int ni = 0; ni < 8; ni++)
                    mma8(acc[mi][ni], Af[mi], Bf[ni]);
        }
    };

    constexpr int KT = KD / BK;
#pragma unroll
    for (int s = 0; s < STAGES - 1; s++) {
        load_stage(s, s);
        asm volatile("cp.async.commit_group;");
    }
    for (int kt = 0; kt < KT; kt++) {
        asm volatile("cp.async.wait_group 1;" ::: "memory");
        __syncthreads();
        const int nt = kt + STAGES - 1;
        if (nt < KT) load_stage(nt % STAGES, nt);
        asm volatile("cp.async.commit_group;");
        compute(kt % STAGES);
    }

    // ------------------------------- epilogue -------------------------------
    const float* bp = bias + (size_t)e * N + col0;
    float2 bv[8];
#pragma unroll
    for (int ni = 0; ni < 8; ni++) {
        const int c = wn * 64 + ni * 8 + 2 * (lane & 3);
        bv[ni] = *(const float2*)(bp + c);
    }
#pragma unroll
    for (int mi = 0; mi < 4; mi++) {
#pragma unroll
        for (int h = 0; h < 2; h++) {
            const int r = row0 + wm * 64 + mi * 16 + (lane >> 2) + h * 8;
            if (r >= cnt) continue;
            float* op;
            if (G1) {
                op = g_h + ((size_t)e * Tn + r) * N;      // N == Hh
            } else {
                const int slot = g_list[e * Tn + r];      // token*2 + k
                op = g_y + (size_t)slot * N;              // N == Dd
            }
#pragma unroll
            for (int ni = 0; ni < 8; ni++) {
                const int c = col0 + wn * 64 + ni * 8 + 2 * (lane & 3);
                float v0 = acc[mi][ni][h * 2 + 0] + bv[ni].x;
                float v1 = acc[mi][ni][h * 2 + 1] + bv[ni].y;
                if (G1) {
                    v0 = f2tf_f(fmaxf(v0, 0.f));   // round once for GEMM2 feed
                    v1 = f2tf_f(fmaxf(v1, 0.f));
                }
                *(float2*)(op + c) = make_float2(v0, v1);
            }
        }
    }
}

// ------------------------------------------------------ gated combine -------
__global__ void combine_kernel(float* __restrict__ out) {
    const int idx = blockIdx.x * 256 + threadIdx.x;
    const int t   = idx / (Dd / 4);
    const int c   = idx % (Dd / 4);
    const float gA = g_gate[2 * t];
    const float gB = g_gate[2 * t + 1];
    const float4* y4 = (const float4*)g_y;
    const float4 ya = y4[(size_t)(2 * t) * (Dd / 4) + c];
    const float4 yb = y4[(size_t)(2 * t + 1) * (Dd / 4) + c];
    float4 o;
    o.x = gA * ya.x + gB * yb.x;
    o.y = gA * ya.y + gB * yb.y;
    o.z = gA * ya.z + gB * yb.z;
    o.w = gA * ya.w + gB * yb.w;
    ((float4*)out)[idx] = o;
}

// ---------------------------------------------------------------- launch ----
extern "C" void kernel_launch(void* const* d_in, const int* in_sizes, int n_in,
                              void* d_out, int out_size) {
    const float* x  = (const float*)d_in[0];   // (B,N,D)
    const float* wg = (const float*)d_in[1];   // (D,E)
    const float* bg = (const float*)d_in[2];   // (E,)
    const float* w1 = (const float*)d_in[3];   // (E,D,H)
    const float* b1 = (const float*)d_in[4];   // (E,H)
    const float* w2 = (const float*)d_in[5];   // (E,H,D)
    const float* b2 = (const float*)d_in[6];   // (E,D)
    float* out = (float*)d_out;

    const int smem_bytes = SMEM_FLOATS * (int)sizeof(float);   // 81408
    cudaFuncSetAttribute(moe_gemm<Hh, Dd, true>,
                         cudaFuncAttributeMaxDynamicSharedMemorySize, smem_bytes);
    cudaFuncSetAttribute(moe_gemm<Dd, Hh, false>,
                         cudaFuncAttributeMaxDynamicSharedMemorySize, smem_bytes);

    init_kernel<<<1, 32>>>();
    routing_kernel<<<Tn / 8, 256>>>(x, wg, bg);
    entropy_kernel<<<1, 1024>>>(out, (out_size > Tn * Dd) ? 1 : 0);

    // tf32 pre-round (elementwise, layout-preserving)
    round_x_kernel<<<(Tn * Dd / 4) / 256, 256>>>(x);
    round_w1_kernel<<<(int)(((size_t)Ee * Dd * Hh / 4) / 256), 256>>>(w1);
    round_w2_kernel<<<(int)(((size_t)Ee * Hh * Dd / 4) / 256), 256>>>(w2);

    moe_gemm<Hh, Dd, true><<<dim3(Tn / BM, Hh / BN, Ee), 256, smem_bytes>>>(b1);
    moe_gemm<Dd, Hh, false><<<dim3(Tn / BM, Dd / BN, Ee), 256, smem_bytes>>>(b2);
    combine_kernel<<<(Tn * Dd / 4) / 256, 256>>>(out);
}

// round 10
// speedup vs baseline: 1.0585x; 1.0585x over previous
#include <cuda_runtime.h>
#include <stdint.h>
#include <math.h>

// Problem constants: B=2, N=2048 -> T=4096 tokens, D=1024, E=8, H=2048, K=2
#define Tn 4096
#define Dd 1024
#define Ee 8
#define Hh 2048

// GEMM tile config: block 128x128, BK=16, 8 warps (2m x 4n), warp tile 64x32.
// Same verified smem layout style as the 570us kernel; smaller N tile to halve
// accumulators and reach 2 CTAs/SM.
#define BM 128
#define BN 128
#define BK 16
#define STAGES 3
#define ASTR 20                      // A smem row stride (floats), conflict-free
#define BSTR 136                     // B smem row stride (floats), == 8 mod 32
#define ASZ (BM * ASTR)              // 2560 floats / stage
#define BSZ (BK * BSTR)              // 2176 floats / stage
#define SMEM_FLOATS (STAGES * (ASZ + BSZ))   // 14208 floats = 56832 B

// ---------------- device scratch (allocation-free rule: __device__ globals) --
__device__ int   g_cnt[Ee];
__device__ int   g_list[Ee * Tn];            // pair slot (= token*2 + k) per expert row
__device__ float g_gate[Tn * 2];
__device__ float g_ent[Tn];
__device__ float g_h[(size_t)Ee * Tn * Hh];  // hidden activations (tf32-rounded)
__device__ float g_y[(size_t)Tn * 2 * Dd];   // per-pair expert outputs
__device__ float g_xt[(size_t)Tn * Dd];      // x, tf32-rounded (same layout)
__device__ float g_w1r[(size_t)Ee * Dd * Hh];// w1, tf32-rounded (same layout)
__device__ float g_w2r[(size_t)Ee * Hh * Dd];// w2, tf32-rounded (same layout)

// -------------------------------------------------------------- helpers -----
__device__ __forceinline__ float f2tf_f(float x) {
    uint32_t r;
    asm("cvt.rna.tf32.f32 %0, %1;" : "=r"(r) : "f"(x));
    return __uint_as_float(r);
}
__device__ __forceinline__ void cp16(float* s, const float* g) {
    uint32_t sa = (uint32_t)__cvta_generic_to_shared(s);
    asm volatile("cp.async.cg.shared.global [%0], [%1], 16;" :: "r"(sa), "l"(g));
}
__device__ __forceinline__ void mma8(float* c, const uint32_t* a, const uint32_t* b) {
    asm volatile(
        "mma.sync.aligned.m16n8k8.row.col.f32.tf32.tf32.f32 "
        "{%0,%1,%2,%3}, {%4,%5,%6,%7}, {%8,%9}, {%0,%1,%2,%3};"
        : "+f"(c[0]), "+f"(c[1]), "+f"(c[2]), "+f"(c[3])
        : "r"(a[0]), "r"(a[1]), "r"(a[2]), "r"(a[3]), "r"(b[0]), "r"(b[1]));
}

// ---------------------------------------------------------------- init ------
__global__ void init_kernel() {
    if (threadIdx.x < Ee) g_cnt[threadIdx.x] = 0;
}

// ------------------------------------------------------------- routing ------
__global__ void routing_kernel(const float* __restrict__ x,
                               const float* __restrict__ wg,
                               const float* __restrict__ bg) {
    const int t    = blockIdx.x * 8 + (threadIdx.x >> 5);
    const int lane = threadIdx.x & 31;
    if (t >= Tn) return;

    float acc[Ee];
#pragma unroll
    for (int e = 0; e < Ee; e++) acc[e] = 0.f;

    const float* xr = x + (size_t)t * Dd;
    for (int c = lane; c < Dd; c += 32) {
        const float xv = xr[c];
        const float4* w4 = reinterpret_cast<const float4*>(wg + (size_t)c * Ee);
        const float4 a = w4[0];
        const float4 b = w4[1];
        acc[0] += xv * a.x; acc[1] += xv * a.y; acc[2] += xv * a.z; acc[3] += xv * a.w;
        acc[4] += xv * b.x; acc[5] += xv * b.y; acc[6] += xv * b.z; acc[7] += xv * b.w;
    }
#pragma unroll
    for (int off = 16; off; off >>= 1) {
#pragma unroll
        for (int e = 0; e < Ee; e++)
            acc[e] += __shfl_xor_sync(0xffffffffu, acc[e], off);
    }

    if (lane == 0) {
        float l[Ee];
#pragma unroll
        for (int e = 0; e < Ee; e++) l[e] = acc[e] + bg[e];

        // top-2 (ties -> lowest index, matching jax.lax.top_k)
        int i0 = 0; float v0 = l[0];
#pragma unroll
        for (int e = 1; e < Ee; e++) if (l[e] > v0) { v0 = l[e]; i0 = e; }
        int i1 = -1; float v1 = -3.4e38f;
#pragma unroll
        for (int e = 0; e < Ee; e++)
            if (e != i0 && l[e] > v1) { v1 = l[e]; i1 = e; }

        const float e1 = expf(v1 - v0);
        const float inv = 1.f / (1.f + e1);
        const float gv0 = inv;
        const float gv1 = e1 * inv;

        g_ent[t] = -(gv0 * logf(fmaxf(gv0, 1e-8f)) +
                     gv1 * logf(fmaxf(gv1, 1e-8f)));

        int p0 = atomicAdd(&g_cnt[i0], 1);
        g_list[i0 * Tn + p0] = t * 2 + 0;
        g_gate[t * 2 + 0] = gv0;

        int p1 = atomicAdd(&g_cnt[i1], 1);
        g_list[i1 * Tn + p1] = t * 2 + 1;
        g_gate[t * 2 + 1] = gv1;
    }
}

// ------------------------------------------------- entropy (deterministic) --
__global__ void entropy_kernel(float* __restrict__ out, int do_write) {
    __shared__ float sh[1024];
    const int t = threadIdx.x;
    float s = 0.f;
    for (int i = t; i < Tn; i += 1024) s += g_ent[i];
    sh[t] = s;
    __syncthreads();
    for (int o = 512; o; o >>= 1) {
        if (t < o) sh[t] += sh[t + o];
        __syncthreads();
    }
    if (t == 0 && do_write) out[(size_t)Tn * Dd] = sh[0] / (float)Tn;
}

// --------------------------------------------- tf32 pre-round (elementwise) -
__global__ void round_x_kernel(const float* __restrict__ x) {
    const int idx = blockIdx.x * 256 + threadIdx.x;       // over Tn*Dd/4
    float4 v = ((const float4*)x)[idx];
    v.x = f2tf_f(v.x); v.y = f2tf_f(v.y); v.z = f2tf_f(v.z); v.w = f2tf_f(v.w);
    ((float4*)g_xt)[idx] = v;
}
__global__ void round_w1_kernel(const float* __restrict__ w1) {
    const size_t idx = (size_t)blockIdx.x * 256 + threadIdx.x;   // over E*D*H/4
    float4 v = ((const float4*)w1)[idx];
    v.x = f2tf_f(v.x); v.y = f2tf_f(v.y); v.z = f2tf_f(v.z); v.w = f2tf_f(v.w);
    ((float4*)g_w1r)[idx] = v;
}
__global__ void round_w2_kernel(const float* __restrict__ w2) {
    const size_t idx = (size_t)blockIdx.x * 256 + threadIdx.x;   // over E*H*D/4
    float4 v = ((const float4*)w2)[idx];
    v.x = f2tf_f(v.x); v.y = f2tf_f(v.y); v.z = f2tf_f(v.z); v.w = f2tf_f(v.w);
    ((float4*)g_w2r)[idx] = v;
}

// ----------------------------------------------------- tf32 grouped GEMM ----
// C[r, col] = A[r, :] @ W_e[:, col] + bias_e[col]   (relu+round+gather if G1,
// scatter-to-pair-slot if !G1). Block 128x128, BK=16, warp tile 64x32,
// 2 CTAs/SM target.
template<int N, int KD, bool G1>
__global__ __launch_bounds__(256, 2)
void moe_gemm(const float* __restrict__ bias)
{
    const int e    = blockIdx.z;
    const int cnt  = g_cnt[e];
    const int row0 = blockIdx.x * BM;
    if (row0 >= cnt) return;
    const int col0 = blockIdx.y * BN;

    extern __shared__ float sm[];
    float* As = sm;                    // [STAGES][BM][ASTR]
    float* Bs = sm + STAGES * ASZ;     // [STAGES][BK][BSTR]

    const int tid  = threadIdx.x;
    const int lane = tid & 31;
    const int warp = tid >> 5;
    const int wm   = warp & 1;         // 2 warps along M (64 rows each)
    const int wn   = warp >> 1;        // 4 warps along N (32 cols each)

    // --- A loader: 2 rows per thread (128 rows x 4 float4 per stage) ---
    const int ar0 = tid >> 2;          // 0..63
    const int ak4 = (tid & 3) * 4;     // k offset within BK (0,4,8,12)
    const float* ap0;
    const float* ap1;
    if (G1) {
        const int t0 = g_list[e * Tn + row0 + ar0] >> 1;
        const int t1 = g_list[e * Tn + row0 + ar0 + 64] >> 1;
        ap0 = g_xt + (size_t)t0 * KD + ak4;
        ap1 = g_xt + (size_t)t1 * KD + ak4;
    } else {
        ap0 = g_h + ((size_t)e * Tn + row0 + ar0) * KD + ak4;
        ap1 = g_h + ((size_t)e * Tn + row0 + ar0 + 64) * KD + ak4;
    }

    // --- B loader: 2 float4 per thread (16 rows x 32 float4 per stage) ---
    const int brow = tid >> 5;         // 0..7, also loads brow+8
    const int bc4  = (lane) * 4;       // 0..124
    const float* W = G1 ? g_w1r : g_w2r;
    const float* Wp = W + (size_t)e * KD * N + col0 + bc4;

    float acc[4][4][4];
#pragma unroll
    for (int mi = 0; mi < 4; mi++)
#pragma unroll
        for (int ni = 0; ni < 4; ni++)
#pragma unroll
            for (int j = 0; j < 4; j++) acc[mi][ni][j] = 0.f;

    auto load_stage = [&](int s, int kt) {
        float* as = As + s * ASZ;
        float* bs = Bs + s * BSZ;
        const int kg = kt * BK;
        cp16(as + ar0 * ASTR + ak4, ap0 + kg);
        cp16(as + (ar0 + 64) * ASTR + ak4, ap1 + kg);
        cp16(bs + brow * BSTR + bc4,       Wp + (size_t)(kg + brow) * N);
        cp16(bs + (brow + 8) * BSTR + bc4, Wp + (size_t)(kg + brow + 8) * N);
    };

    auto compute = [&](int s) {
        const float* as = As + s * ASZ;
        const float* bs = Bs + s * BSZ;
#pragma unroll
        for (int g = 0; g < 2; g++) {              // two k8 steps per BK=16
            uint32_t Af[4][4];
#pragma unroll
            for (int mi = 0; mi < 4; mi++) {
                const int r = wm * 64 + mi * 16 + (lane >> 2);
                const int k = g * 8 + (lane & 3);
                const float* p = as + r * ASTR + k;
                Af[mi][0] = __float_as_uint(p[0]);            // (r,   k)
                Af[mi][1] = __float_as_uint(p[8 * ASTR]);     // (r+8, k)
                Af[mi][2] = __float_as_uint(p[4]);            // (r,   k+4)
                Af[mi][3] = __float_as_uint(p[8 * ASTR + 4]); // (r+8, k+4)
            }
            uint32_t Bf[4][2];
#pragma unroll
            for (int ni = 0; ni < 4; ni++) {
                const int c = wn * 32 + ni * 8 + (lane >> 2);
                const int k = g * 8 + (lane & 3);
                const float* p = bs + k * BSTR + c;
                Bf[ni][0] = __float_as_uint(p[0]);            // (k,   c)
                Bf[ni][1] = __float_as_uint(p[4 * BSTR]);     // (k+4, c)
            }
#pragma unroll
            for (int mi = 0; mi < 4; mi++)
#pragma unroll
                for (int ni = 0; ni < 4; ni++)
                    mma8(acc[mi][ni], Af[mi], Bf[ni]);
        }
    };

    constexpr int KT = KD / BK;
#pragma unroll
    for (int s = 0; s < STAGES - 1; s++) {
        load_stage(s, s);
        asm volatile("cp.async.commit_group;");
    }
    for (int kt = 0; kt < KT; kt++) {
        asm volatile("cp.async.wait_group 1;" ::: "memory");
        __syncthreads();
        const int nt = kt + STAGES - 1;
        if (nt < KT) load_stage(nt % STAGES, nt);
        asm volatile("cp.async.commit_group;");
        compute(kt % STAGES);
    }

    // ------------------------------- epilogue -------------------------------
    const float* bp = bias + (size_t)e * N + col0;
    float2 bv[4];
#pragma unroll
    for (int ni = 0; ni < 4; ni++) {
        const int c = wn * 32 + ni * 8 + 2 * (lane & 3);
        bv[ni] = *(const float2*)(bp + c);
    }
#pragma unroll
    for (int mi = 0; mi < 4; mi++) {
#pragma unroll
        for (int h = 0; h < 2; h++) {
            const int r = row0 + wm * 64 + mi * 16 + (lane >> 2) + h * 8;
            if (r >= cnt) continue;
            float* op;
            if (G1) {
                op = g_h + ((size_t)e * Tn + r) * N;      // N == Hh
            } else {
                const int slot = g_list[e * Tn + r];      // token*2 + k
                op = g_y + (size_t)slot * N;              // N == Dd
            }
#pragma unroll
            for (int ni = 0; ni < 4; ni++) {
                const int c = col0 + wn * 32 + ni * 8 + 2 * (lane & 3);
                float v0 = acc[mi][ni][h * 2 + 0] + bv[ni].x;
                float v1 = acc[mi][ni][h * 2 + 1] + bv[ni].y;
                if (G1) {
                    v0 = f2tf_f(fmaxf(v0, 0.f));   // round once for GEMM2 feed
                    v1 = f2tf_f(fmaxf(v1, 0.f));
                }
                *(float2*)(op + c) = make_float2(v0, v1);
            }
        }
    }
}

// ------------------------------------------------------ gated combine -------
__global__ void combine_kernel(float* __restrict__ out) {
    const int idx = blockIdx.x * 256 + threadIdx.x;
    const int t   = idx / (Dd / 4);
    const int c   = idx % (Dd / 4);
    const float gA = g_gate[2 * t];
    const float gB = g_gate[2 * t + 1];
    const float4* y4 = (const float4*)g_y;
    const float4 ya = y4[(size_t)(2 * t) * (Dd / 4) + c];
    const float4 yb = y4[(size_t)(2 * t + 1) * (Dd / 4) + c];
    float4 o;
    o.x = gA * ya.x + gB * yb.x;
    o.y = gA * ya.y + gB * yb.y;
    o.z = gA * ya.z + gB * yb.z;
    o.w = gA * ya.w + gB * yb.w;
    ((float4*)out)[idx] = o;
}

// ---------------------------------------------------------------- launch ----
extern "C" void kernel_launch(void* const* d_in, const int* in_sizes, int n_in,
                              void* d_out, int out_size) {
    const float* x  = (const float*)d_in[0];   // (B,N,D)
    const float* wg = (const float*)d_in[1];   // (D,E)
    const float* bg = (const float*)d_in[2];   // (E,)
    const float* w1 = (const float*)d_in[3];   // (E,D,H)
    const float* b1 = (const float*)d_in[4];   // (E,H)
    const float* w2 = (const float*)d_in[5];   // (E,H,D)
    const float* b2 = (const float*)d_in[6];   // (E,D)
    float* out = (float*)d_out;

    const int smem_bytes = SMEM_FLOATS * (int)sizeof(float);   // 56832
    cudaFuncSetAttribute(moe_gemm<Hh, Dd, true>,
                         cudaFuncAttributeMaxDynamicSharedMemorySize, smem_bytes);
    cudaFuncSetAttribute(moe_gemm<Dd, Hh, false>,
                         cudaFuncAttributeMaxDynamicSharedMemorySize, smem_bytes);

    init_kernel<<<1, 32>>>();
    routing_kernel<<<Tn / 8, 256>>>(x, wg, bg);
    entropy_kernel<<<1, 1024>>>(out, (out_size > Tn * Dd) ? 1 : 0);

    // tf32 pre-round (elementwise, layout-preserving)
    round_x_kernel<<<(Tn * Dd / 4) / 256, 256>>>(x);
    round_w1_kernel<<<(int)(((size_t)Ee * Dd * Hh / 4) / 256), 256>>>(w1);
    round_w2_kernel<<<(int)(((size_t)Ee * Hh * Dd / 4) / 256), 256>>>(w2);

    moe_gemm<Hh, Dd, true><<<dim3(Tn / BM, Hh / BN, Ee), 256, smem_bytes>>>(b1);
    moe_gemm<Dd, Hh, false><<<dim3(Tn / BM, Dd / BN, Ee), 256, smem_bytes>>>(b2);
    combine_kernel<<<(Tn * Dd / 4) / 256, 256>>>(out);
}